// round 8
// baseline (speedup 1.0000x reference)
#include <cuda_runtime.h>
#include <math_constants.h>

// Split-K persistent MAM-GEMM, single launch, in-kernel finisher merge.
// 128 output tiles of 128x128  x  8 K-splits (128 k each) = 1024 items over
// 148 persistent CTAs (98.8% balance). Fat TM8xTN8 microtile (measured-best
// per-SM alu efficiency). Exclusive partial stores; last-arriving CTA per tile
// merges all 8 partials + bias into C.

#define TBM 128
#define TBN 128
#define BK  16
#define TM  8
#define TN  8
#define SA  132     // 132*4 % 16 == 0 -> LDS.128 aligned
#define NUM_SMS 148
#define SPLITS  8
#define THREADS 256

#define MM 2048
#define NN 1024
#define NTILES ((MM / TBM) * (NN / TBN))   // 128

__device__ float g_mx[SPLITS][MM * NN];    // 64 MB
__device__ float g_mn[SPLITS][MM * NN];    // 64 MB
__device__ unsigned int g_cnt[NTILES];     // zeroed at load; finisher resets -> replay-safe

__global__ __launch_bounds__(THREADS, 1)
void mam_kernel(const float* __restrict__ A,    // [M, K]
                const float* __restrict__ W,    // [N, K]
                const float* __restrict__ bias, // [N]
                float* __restrict__ C,          // [M, N]
                int M, int N, int K)
{
    __shared__ float As[2][BK * SA];  // As[buf][k*SA + m]
    __shared__ float Bs[2][BK * SA];  // Bs[buf][k*SA + n]
    __shared__ unsigned int s_old;

    const int tid = threadIdx.x;
    const int tx  = tid & 15;    // 16 col-groups of TN=8 -> 128 cols
    const int ty  = tid >> 4;    // 16 row-groups of TM=8 -> 128 rows

    // staging: 128x16 floats per operand = 256 threads x 2 float4 (rows lrow, lrow+64)
    const int lrow = tid >> 2;        // 0..63
    const int lcol = (tid & 3) * 4;   // 0,4,8,12

    const int tilesN = N / TBN;                   // 8
    const int nTiles = (M / TBM) * tilesN;        // 128
    const int nItems = nTiles * SPLITS;           // 1024
    const int kPart  = K / SPLITS;                // 128
    const int nK     = kPart / BK;                // 8

    for (int t = blockIdx.x; t < nItems; t += NUM_SMS) {
        const int tile  = t & (nTiles - 1);
        const int split = t >> 7;
        const int mi = tile >> 3;
        const int ni = tile & 7;
        const int kbase = split * kPart;

        const float* Aptr = A + (size_t)(mi * TBM + lrow) * K + kbase + lcol;
        const float* Wptr = W + (size_t)(ni * TBN + lrow) * K + kbase + lcol;
        const size_t rowskip = (size_t)64 * K;

        float mx[TM][TN], mn[TM][TN];
#pragma unroll
        for (int i = 0; i < TM; ++i)
#pragma unroll
            for (int j = 0; j < TN; ++j) {
                mx[i][j] = -CUDART_INF_F;
                mn[i][j] =  CUDART_INF_F;
            }

        // ---- prologue: stage k-slice 0 into buf 0 ----
        float4 pa0 = *(const float4*)(Aptr);
        float4 pa1 = *(const float4*)(Aptr + rowskip);
        float4 pb0 = *(const float4*)(Wptr);
        float4 pb1 = *(const float4*)(Wptr + rowskip);
        {
            float* as = As[0]; float* bs = Bs[0];
            as[(lcol + 0) * SA + lrow] = pa0.x;
            as[(lcol + 1) * SA + lrow] = pa0.y;
            as[(lcol + 2) * SA + lrow] = pa0.z;
            as[(lcol + 3) * SA + lrow] = pa0.w;
            as[(lcol + 0) * SA + lrow + 64] = pa1.x;
            as[(lcol + 1) * SA + lrow + 64] = pa1.y;
            as[(lcol + 2) * SA + lrow + 64] = pa1.z;
            as[(lcol + 3) * SA + lrow + 64] = pa1.w;
            bs[(lcol + 0) * SA + lrow] = pb0.x;
            bs[(lcol + 1) * SA + lrow] = pb0.y;
            bs[(lcol + 2) * SA + lrow] = pb0.z;
            bs[(lcol + 3) * SA + lrow] = pb0.w;
            bs[(lcol + 0) * SA + lrow + 64] = pb1.x;
            bs[(lcol + 1) * SA + lrow + 64] = pb1.y;
            bs[(lcol + 2) * SA + lrow + 64] = pb1.z;
            bs[(lcol + 3) * SA + lrow + 64] = pb1.w;
        }
        __syncthreads();

        for (int kt = 0; kt < nK; ++kt) {
            const int buf = kt & 1;

            if (kt + 1 < nK) {
                const int k0 = (kt + 1) * BK;
                pa0 = *(const float4*)(Aptr + k0);
                pa1 = *(const float4*)(Aptr + rowskip + k0);
                pb0 = *(const float4*)(Wptr + k0);
                pb1 = *(const float4*)(Wptr + rowskip + k0);
            }

            const float* as = As[buf];
            const float* bs = Bs[buf];
#pragma unroll 8
            for (int k = 0; k < BK; ++k) {
                float a[TM], b[TN];
                *(float4*)&a[0] = *(const float4*)&as[k * SA + ty * TM];
                *(float4*)&a[4] = *(const float4*)&as[k * SA + ty * TM + 4];
                *(float4*)&b[0] = *(const float4*)&bs[k * SA + tx * TN];
                *(float4*)&b[4] = *(const float4*)&bs[k * SA + tx * TN + 4];
#pragma unroll
                for (int i = 0; i < TM; ++i)
#pragma unroll
                    for (int j = 0; j < TN; ++j) {
                        float p = a[i] * b[j];
                        mx[i][j] = fmaxf(mx[i][j], p);
                        mn[i][j] = fminf(mn[i][j], p);
                    }
            }

            if (kt + 1 < nK) {
                float* asw = As[buf ^ 1]; float* bsw = Bs[buf ^ 1];
                asw[(lcol + 0) * SA + lrow] = pa0.x;
                asw[(lcol + 1) * SA + lrow] = pa0.y;
                asw[(lcol + 2) * SA + lrow] = pa0.z;
                asw[(lcol + 3) * SA + lrow] = pa0.w;
                asw[(lcol + 0) * SA + lrow + 64] = pa1.x;
                asw[(lcol + 1) * SA + lrow + 64] = pa1.y;
                asw[(lcol + 2) * SA + lrow + 64] = pa1.z;
                asw[(lcol + 3) * SA + lrow + 64] = pa1.w;
                bsw[(lcol + 0) * SA + lrow] = pb0.x;
                bsw[(lcol + 1) * SA + lrow] = pb0.y;
                bsw[(lcol + 2) * SA + lrow] = pb0.z;
                bsw[(lcol + 3) * SA + lrow] = pb0.w;
                bsw[(lcol + 0) * SA + lrow + 64] = pb1.x;
                bsw[(lcol + 1) * SA + lrow + 64] = pb1.y;
                bsw[(lcol + 2) * SA + lrow + 64] = pb1.z;
                bsw[(lcol + 3) * SA + lrow + 64] = pb1.w;
                __syncthreads();
            }
        }

        // ---- epilogue: exclusive-owner partial stores ----
        const int row0 = mi * TBM + ty * TM;
        const int col0 = ni * TBN + tx * TN;
        float* mxp = g_mx[split] + (size_t)row0 * N + col0;
        float* mnp = g_mn[split] + (size_t)row0 * N + col0;
#pragma unroll
        for (int i = 0; i < TM; ++i) {
            *(float4*)(mxp + (size_t)i * N)     = make_float4(mx[i][0], mx[i][1], mx[i][2], mx[i][3]);
            *(float4*)(mxp + (size_t)i * N + 4) = make_float4(mx[i][4], mx[i][5], mx[i][6], mx[i][7]);
            *(float4*)(mnp + (size_t)i * N)     = make_float4(mn[i][0], mn[i][1], mn[i][2], mn[i][3]);
            *(float4*)(mnp + (size_t)i * N + 4) = make_float4(mn[i][4], mn[i][5], mn[i][6], mn[i][7]);
        }

        // ---- arrival protocol ----
        __threadfence();                 // release partial stores (gpu scope)
        __syncthreads();                 // all threads done (also orders smem reuse)
        if (tid == 0) s_old = atomicAdd(&g_cnt[tile], 1u);
        __syncthreads();

        if (s_old == SPLITS - 1) {
            // ---- finisher: merge 8 partials + bias -> C ----
            __threadfence();             // acquire other CTAs' partials
            const int rowbase = mi * TBM;
            const int colbase = ni * TBN;
            // 128x128 tile = 16384 elems = 256 threads x 16 float4
#pragma unroll 4
            for (int it = 0; it < 16; ++it) {
                const int e = it * 1024 + tid * 4;
                const int r = e >> 7;
                const int c = e & 127;
                const size_t off = (size_t)(rowbase + r) * N + colbase + c;

                float4 xm = *(const float4*)(g_mx[0] + off);
                float4 nm = *(const float4*)(g_mn[0] + off);
#pragma unroll
                for (int s = 1; s < SPLITS; ++s) {
                    float4 xs = *(const float4*)(g_mx[s] + off);
                    float4 ns = *(const float4*)(g_mn[s] + off);
                    xm.x = fmaxf(xm.x, xs.x); xm.y = fmaxf(xm.y, xs.y);
                    xm.z = fmaxf(xm.z, xs.z); xm.w = fmaxf(xm.w, xs.w);
                    nm.x = fminf(nm.x, ns.x); nm.y = fminf(nm.y, ns.y);
                    nm.z = fminf(nm.z, ns.z); nm.w = fminf(nm.w, ns.w);
                }
                float4 bv = *(const float4*)&bias[colbase + c];
                float4 o;
                o.x = xm.x + nm.x + bv.x;
                o.y = xm.y + nm.y + bv.y;
                o.z = xm.z + nm.z + bv.z;
                o.w = xm.w + nm.w + bv.w;
                *(float4*)(C + off) = o;
            }
            if (tid == 0) g_cnt[tile] = 0;   // reset for next graph replay
        }
    }
}

extern "C" void kernel_launch(void* const* d_in, const int* in_sizes, int n_in,
                              void* d_out, int out_size)
{
    const float* x    = (const float*)d_in[0];   // [M, K]
    const float* w    = (const float*)d_in[1];   // [N, K]
    const float* bias = (const float*)d_in[2];   // [N]
    float* out = (float*)d_out;

    const int N = in_sizes[2];                  // 1024
    const int K = in_sizes[1] / N;              // 1024
    const int M = in_sizes[0] / K;              // 2048

    mam_kernel<<<NUM_SMS, THREADS>>>(x, w, bias, out, M, N, K);
}